// round 4
// baseline (speedup 1.0000x reference)
#include <cuda_runtime.h>
#include <cuda_bf16.h>
#include <math.h>

// ---------------------------------------------------------------------------
// MultiDEQPDEBlock: DEQ fixed-point PDE solver  (B=8, 256x256, hid=32, GN4)
// core_f: conv3x3(4->32) -> GN(4) -> GELU(erf) -> conv3x3(32->1) -> damped update
// Iteration diverges (|1-mask|>1 pixels) -> values ~1e37; all overflow paths
// mirror jax semantics (var->inf, rstd->0, xn->0; NaN diff stops loop).
// 2 kernels/iter: conv1(+GN stats via last-block), fused2(+diff via last-block)
// ---------------------------------------------------------------------------

#define BATCH 8
#define HH 256
#define WW 256
#define PIX (HH*WW)
#define HID 32
#define SHID 16
#define GROUPS 4
#define CPG 8
#define EPS 1e-5f
#define TOL 1e-4f
#define MAX_ITER 50
#define CFL_SCALE 0.015625f
#define NBLK 2048               // 16*16*8 blocks in conv/fused grids

// ---- scratch (device globals; no cudaMalloc allowed) ----
__device__ float g_h[(size_t)BATCH*HID*PIX];      // 64 MB conv1 output (pre-GN)
__device__ float g_sh[(size_t)BATCH*SHID*PIX];    // 32 MB stabilizer hidden
__device__ float g_alpha[(size_t)BATCH*PIX];
__device__ float g_z[(size_t)BATCH*PIX];
__device__ float g_gamma[BATCH];
__device__ float g_part[BATCH*256*GROUPS*2];
__device__ float g_scale[BATCH*HID];
__device__ float g_shift[BATCH*HID];
__device__ float g_diffpart[BATCH*256];
__device__ int   g_converged;
__device__ unsigned g_cnt1;     // zero-init; self-resetting via atomicInc wrap
__device__ unsigned g_cnt2;

__device__ __forceinline__ float gelu_f(float x) {
    return 0.5f * x * (1.0f + erff(x * 0.70710678118654752f));
}
__device__ __forceinline__ float sigmoid_f(float x) {
    return 1.0f / (1.0f + expf(-x));
}

// ---------------------------------------------------------------------------
__global__ void init_kernel(const float* __restrict__ inp) {
    int idx = blockIdx.x * 256 + threadIdx.x;
    if (idx == 0) { g_converged = 0; }
    if (idx < BATCH * PIX) {
        int b = idx >> 16, pix = idx & 65535;
        g_z[idx] = inp[(size_t)b * 3 * PIX + pix];
    }
}

// ---------------------------------------------------------------------------
// stabilizer conv1: 3->16, GELU (one-time)
// ---------------------------------------------------------------------------
__global__ void __launch_bounds__(256) stab1_kernel(
    const float* __restrict__ inp, const float* __restrict__ w,
    const float* __restrict__ bias)
{
    const int b = blockIdx.z;
    const int tx0 = blockIdx.x * 16, ty0 = blockIdx.y * 16;
    __shared__ float s_in[3][18][18];
    __shared__ float s_w[27][16];
    __shared__ float s_b[16];
    int tid = threadIdx.y * 16 + threadIdx.x;

    for (int i = tid; i < SHID * 27; i += 256) {
        int oc = i / 27, r = i % 27;
        s_w[r][oc] = w[i];
    }
    if (tid < SHID) s_b[tid] = bias[tid];

    const float* bp = inp + (size_t)b * 3 * PIX;
    for (int i = tid; i < 3 * 324; i += 256) {
        int c = i / 324, r = i % 324, yy = r / 18, xx = r % 18;
        int gy = ty0 + yy - 1, gx = tx0 + xx - 1;
        float v = 0.f;
        if ((unsigned)gy < 256u && (unsigned)gx < 256u)
            v = bp[c * PIX + gy * WW + gx];
        s_in[c][yy][xx] = v;
    }
    __syncthreads();

    int ty = threadIdx.y, tx = threadIdx.x;
    float in[27];
#pragma unroll
    for (int c = 0; c < 3; c++)
#pragma unroll
        for (int ky = 0; ky < 3; ky++)
#pragma unroll
            for (int kx = 0; kx < 3; kx++)
                in[c * 9 + ky * 3 + kx] = s_in[c][ty + ky][tx + kx];

    float acc[SHID];
#pragma unroll
    for (int oc = 0; oc < SHID; oc++) acc[oc] = s_b[oc];
#pragma unroll
    for (int r = 0; r < 27; r++) {
        float iv = in[r];
#pragma unroll
        for (int j = 0; j < 4; j++) {
            float4 w4 = ((const float4*)&s_w[r][0])[j];
            acc[4*j+0] += iv * w4.x; acc[4*j+1] += iv * w4.y;
            acc[4*j+2] += iv * w4.z; acc[4*j+3] += iv * w4.w;
        }
    }

    int pix = (ty0 + ty) * WW + (tx0 + tx);
    float* out = g_sh + (size_t)b * SHID * PIX + pix;
#pragma unroll
    for (int oc = 0; oc < SHID; oc++)
        out[oc * PIX] = gelu_f(acc[oc]);
}

// ---------------------------------------------------------------------------
// stabilizer conv2: 16->1, sigmoid -> alpha (one-time)
// ---------------------------------------------------------------------------
__global__ void __launch_bounds__(256) stab2_kernel(
    const float* __restrict__ w, const float* __restrict__ bias)
{
    const int b = blockIdx.z;
    const int tx0 = blockIdx.x * 16, ty0 = blockIdx.y * 16;
    __shared__ float s_in[SHID][18][18];
    __shared__ float s_w[SHID * 9];
    int tid = threadIdx.y * 16 + threadIdx.x;

    if (tid < SHID * 9) s_w[tid] = w[tid];
    const float* hp = g_sh + (size_t)b * SHID * PIX;
    for (int i = tid; i < SHID * 324; i += 256) {
        int c = i / 324, r = i % 324, yy = r / 18, xx = r % 18;
        int gy = ty0 + yy - 1, gx = tx0 + xx - 1;
        float v = 0.f;
        if ((unsigned)gy < 256u && (unsigned)gx < 256u)
            v = hp[c * PIX + gy * WW + gx];
        s_in[c][yy][xx] = v;
    }
    __syncthreads();

    int ty = threadIdx.y, tx = threadIdx.x;
    float acc = bias[0];
#pragma unroll
    for (int c = 0; c < SHID; c++)
#pragma unroll
        for (int ky = 0; ky < 3; ky++)
#pragma unroll
            for (int kx = 0; kx < 3; kx++)
                acc += s_w[c * 9 + ky * 3 + kx] * s_in[c][ty + ky][tx + kx];

    int pix = (ty0 + ty) * WW + (tx0 + tx);
    g_alpha[(size_t)b * PIX + pix] = sigmoid_f(acc);
}

// ---------------------------------------------------------------------------
// spec_ctrl: per-batch stats -> tiny MLP -> gamma[b]  (one-time, 1024 thr)
// ---------------------------------------------------------------------------
__global__ void __launch_bounds__(1024) spec_kernel(
    const float* __restrict__ inp,
    const float* __restrict__ fc1_w, const float* __restrict__ fc1_b,
    const float* __restrict__ fc2_w, const float* __restrict__ fc2_b)
{
    const int b = blockIdx.x;
    int tid = threadIdx.x;
    const float* bp = inp + (size_t)b * 3 * PIX;
    const float* kp = bp + 2 * PIX;
    float s1 = 0.f, q1 = 0.f, s2 = 0.f, q2 = 0.f;
    for (int i = tid; i < PIX; i += 1024) {
        float bv = fabsf(bp[i]);
        s1 += bv; q1 += bv * bv;
        float kv = kp[i];
        s2 += kv; q2 += kv * kv;
    }
#pragma unroll
    for (int o = 16; o > 0; o >>= 1) {
        s1 += __shfl_down_sync(0xffffffffu, s1, o);
        q1 += __shfl_down_sync(0xffffffffu, q1, o);
        s2 += __shfl_down_sync(0xffffffffu, s2, o);
        q2 += __shfl_down_sync(0xffffffffu, q2, o);
    }
    __shared__ float red[32][4];
    int lane = tid & 31, warp = tid >> 5;
    if (lane == 0) { red[warp][0] = s1; red[warp][1] = q1; red[warp][2] = s2; red[warp][3] = q2; }
    __syncthreads();
    if (tid == 0) {
        float S1 = 0, Q1 = 0, S2 = 0, Q2 = 0;
#pragma unroll
        for (int w = 0; w < 32; w++) { S1 += red[w][0]; Q1 += red[w][1]; S2 += red[w][2]; Q2 += red[w][3]; }
        const float N = (float)PIX;
        float m1 = S1 / N, m2 = S2 / N;
        float v1 = (Q1 - N * m1 * m1) / (N - 1.0f);
        float v2 = (Q2 - N * m2 * m2) / (N - 1.0f);
        float feat[5] = { m1, sqrtf(fmaxf(v1, 0.f)), m2, sqrtf(fmaxf(v2, 0.f)), 1.0f };
        float out = fc2_b[0];
        for (int j = 0; j < 32; j++) {
            float t = fc1_b[j];
#pragma unroll
            for (int i = 0; i < 5; i++) t += feat[i] * fc1_w[j * 5 + i];
            out += gelu_f(t) * fc2_w[j];
        }
        g_gamma[b] = (0.5f + 1.5f * sigmoid_f(out)) * CFL_SCALE;
    }
}

// ---------------------------------------------------------------------------
// core conv1: [z,b,m,k](4)->32, write g_h, GN partials; LAST BLOCK folds stats
// ---------------------------------------------------------------------------
__global__ void __launch_bounds__(256) conv1_kernel(
    const float* __restrict__ inp, const float* __restrict__ w1,
    const float* __restrict__ b1, const float* __restrict__ gn_w,
    const float* __restrict__ gn_b, int check)
{
    if (check && g_converged) return;
    const int b = blockIdx.z;
    const int tx0 = blockIdx.x * 16, ty0 = blockIdx.y * 16;
    __shared__ float s_in[4][18][18];
    __shared__ float s_w[36][32];
    __shared__ float s_b[32];
    __shared__ float s_red[8][8];
    __shared__ bool s_last;
    int tid = threadIdx.y * 16 + threadIdx.x;

    for (int i = tid; i < HID * 36; i += 256) {
        int oc = i / 36, r = i % 36;
        s_w[r][oc] = w1[i];
    }
    if (tid < HID) s_b[tid] = b1[tid];

    const float* zp = g_z + (size_t)b * PIX;
    const float* bp = inp + (size_t)b * 3 * PIX;
    for (int i = tid; i < 4 * 324; i += 256) {
        int c = i / 324, r = i % 324, yy = r / 18, xx = r % 18;
        int gy = ty0 + yy - 1, gx = tx0 + xx - 1;
        float v = 0.f;
        if ((unsigned)gy < 256u && (unsigned)gx < 256u) {
            int off = gy * WW + gx;
            v = (c == 0) ? zp[off] : bp[(c - 1) * PIX + off];
        }
        s_in[c][yy][xx] = v;
    }
    __syncthreads();

    int ty = threadIdx.y, tx = threadIdx.x;
    float in[36];
#pragma unroll
    for (int c = 0; c < 4; c++)
#pragma unroll
        for (int ky = 0; ky < 3; ky++)
#pragma unroll
            for (int kx = 0; kx < 3; kx++)
                in[c * 9 + ky * 3 + kx] = s_in[c][ty + ky][tx + kx];

    float acc[HID];
#pragma unroll
    for (int oc = 0; oc < HID; oc++) acc[oc] = s_b[oc];
#pragma unroll
    for (int r = 0; r < 36; r++) {
        float iv = in[r];
#pragma unroll
        for (int j = 0; j < 8; j++) {
            float4 w4 = ((const float4*)&s_w[r][0])[j];   // LDS.128 broadcast
            acc[4*j+0] += iv * w4.x; acc[4*j+1] += iv * w4.y;
            acc[4*j+2] += iv * w4.z; acc[4*j+3] += iv * w4.w;
        }
    }

    int pix = (ty0 + ty) * WW + (tx0 + tx);
    float* hp = g_h + (size_t)b * HID * PIX + pix;
    float gs[4] = {0, 0, 0, 0}, gq[4] = {0, 0, 0, 0};
#pragma unroll
    for (int oc = 0; oc < HID; oc++) {
        float v = acc[oc];
        hp[oc * PIX] = v;
        gs[oc >> 3] += v;
        gq[oc >> 3] += v * v;
    }
#pragma unroll
    for (int o = 16; o > 0; o >>= 1) {
#pragma unroll
        for (int g = 0; g < 4; g++) {
            gs[g] += __shfl_down_sync(0xffffffffu, gs[g], o);
            gq[g] += __shfl_down_sync(0xffffffffu, gq[g], o);
        }
    }
    int lane = tid & 31, warp = tid >> 5;
    if (lane == 0) {
#pragma unroll
        for (int g = 0; g < 4; g++) { s_red[warp][g] = gs[g]; s_red[warp][4 + g] = gq[g]; }
    }
    __syncthreads();
    int blin = blockIdx.y * 16 + blockIdx.x;
    if (tid < 8) {
        float v = 0.f;
#pragma unroll
        for (int w = 0; w < 8; w++) v += s_red[w][tid];
        int g = tid & 3, which = tid >> 2;
        g_part[((b * 256 + blin) * 4 + g) * 2 + which] = v;
        __threadfence();
    }
    __syncthreads();
    if (tid == 0) {
        unsigned old = atomicInc(&g_cnt1, NBLK - 1u);   // wraps to 0 -> replay-safe
        s_last = (old == NBLK - 1u);
    }
    __syncthreads();
    if (!s_last) return;
    __threadfence();

    // last block: fold GN stats for all 32 (b,g) pairs; 8 lanes per pair
    int pair = tid >> 3, l8 = tid & 7;     // pair = bb*4 + g
    int bb = pair >> 2, g = pair & 3;
    float s = 0.f, q = 0.f;
    for (int i = l8; i < 256; i += 8) {
        s += g_part[((bb * 256 + i) * 4 + g) * 2 + 0];
        q += g_part[((bb * 256 + i) * 4 + g) * 2 + 1];
    }
#pragma unroll
    for (int o = 4; o > 0; o >>= 1) {
        s += __shfl_down_sync(0xffffffffu, s, o, 8);
        q += __shfl_down_sync(0xffffffffu, q, o, 8);
    }
    if (l8 == 0) {
        const float invN = 1.0f / (float)(CPG * PIX);
        float mean = s * invN;
        float Qn = q * invN;
        float var = isinf(Qn) ? Qn : fmaxf(Qn - mean * mean, 0.0f);
        float rstd = rsqrtf(var + EPS);                 // var=inf -> rstd=0
#pragma unroll
        for (int c = 0; c < CPG; c++) {
            int gc = g * CPG + c;
            float sc = gn_w[gc] * rstd;
            g_scale[bb * HID + gc] = sc;
            g_shift[bb * HID + gc] = (rstd == 0.0f) ? gn_b[gc] : (gn_b[gc] - mean * sc);
        }
    }
}

// ---------------------------------------------------------------------------
// fused2: GN->GELU->conv2(32->1)->damped update; LAST BLOCK folds diff
//   s_h layout: [pixel(18x18)][36 floats (32 ch + pad)] -> float4 over channels
// ---------------------------------------------------------------------------
__global__ void __launch_bounds__(256) fused2_kernel(
    const float* __restrict__ inp, const float* __restrict__ w2,
    const float* __restrict__ b2, float* __restrict__ final_out, int mode)
{
    if (mode == 0 && g_converged) return;
    const int b = blockIdx.z;
    const int tx0 = blockIdx.x * 16, ty0 = blockIdx.y * 16;
    __shared__ float s_h[324 * 36];        // 46656 B
    __shared__ float s_wt[9 * 32];         // transposed: [pos][c]
    __shared__ float s_sc[HID], s_sf[HID];
    __shared__ float s_red[8];
    __shared__ bool s_last;
    int tid = threadIdx.y * 16 + threadIdx.x;

    for (int i = tid; i < HID * 9; i += 256) {
        int c = i / 9, pos = i % 9;
        s_wt[pos * 32 + c] = w2[i];
    }
    if (tid < HID) { s_sc[tid] = g_scale[b * HID + tid]; s_sf[tid] = g_shift[b * HID + tid]; }
    __syncthreads();

    const float* hp = g_h + (size_t)b * HID * PIX;
    for (int p = tid; p < 324; p += 256) {
        int yy = p / 18, xx = p % 18;
        int gy = ty0 + yy - 1, gx = tx0 + xx - 1;
        bool inb = ((unsigned)gy < 256u) && ((unsigned)gx < 256u);
        int goff = gy * WW + gx;
        float4* dst = (float4*)&s_h[p * 36];
#pragma unroll
        for (int c4 = 0; c4 < 8; c4++) {
            float4 v = make_float4(0.f, 0.f, 0.f, 0.f);
            if (inb) {
                float r[4];
#pragma unroll
                for (int e = 0; e < 4; e++) {
                    int c = c4 * 4 + e;
                    float hv = hp[c * PIX + goff];
                    float sc = s_sc[c];
                    // sc==0 <=> overflow regime (hv may be inf); ref gives gn_b
                    float t = (sc == 0.0f) ? s_sf[c] : (hv * sc + s_sf[c]);
                    r[e] = gelu_f(t);
                }
                v = make_float4(r[0], r[1], r[2], r[3]);
            }
            dst[c4] = v;
        }
    }
    __syncthreads();

    int ty = threadIdx.y, tx = threadIdx.x;
    float a0 = 0.f, a1 = 0.f, a2 = 0.f, a3 = 0.f;
#pragma unroll
    for (int ky = 0; ky < 3; ky++)
#pragma unroll
        for (int kx = 0; kx < 3; kx++) {
            const float4* h4 = (const float4*)&s_h[((ty + ky) * 18 + tx + kx) * 36];
            const float4* w4 = (const float4*)&s_wt[(ky * 3 + kx) * 32];
#pragma unroll
            for (int j = 0; j < 8; j++) {
                float4 h = h4[j], w = w4[j];
                a0 += h.x * w.x; a1 += h.y * w.y;
                a2 += h.z * w.z; a3 += h.w * w.w;
            }
        }
    float acc = b2[0] + ((a0 + a1) + (a2 + a3));

    int pix = (ty0 + ty) * WW + (tx0 + tx);
    int off = b * PIX + pix;
    const float* bp = inp + (size_t)b * 3 * PIX;
    float zold = g_z[off];
    // mirror XLA elementwise rounding exactly (no FMA contraction)
    float ga   = __fmul_rn(g_gamma[b], g_alpha[off]);
    float znew = __fadd_rn(zold, __fmul_rn(ga, acc));
    float m  = bp[PIX + pix];
    float bv = bp[pix];
    float res = __fadd_rn(__fmul_rn(znew, __fadd_rn(1.0f, -m)), __fmul_rn(bv, m));

    if (mode != 0) { final_out[off] = res; return; }

    g_z[off] = res;
    float d = __fadd_rn(res, -zold);
    float s = d * d;
#pragma unroll
    for (int o = 16; o > 0; o >>= 1) s += __shfl_down_sync(0xffffffffu, s, o);
    int lane = tid & 31, warp = tid >> 5;
    if (lane == 0) s_red[warp] = s;
    __syncthreads();
    int blin = blockIdx.y * 16 + blockIdx.x;
    if (tid == 0) {
        float t = 0.f;
#pragma unroll
        for (int w = 0; w < 8; w++) t += s_red[w];
        g_diffpart[b * 256 + blin] = t;
        __threadfence();
        unsigned old = atomicInc(&g_cnt2, NBLK - 1u);
        s_last = (old == NBLK - 1u);
    }
    __syncthreads();
    if (!s_last) return;
    __threadfence();

    // last block: diff = mean_b ||dz_b||; jax cond continues while diff>=TOL
    int w = tid >> 5, l = tid & 31;       // warp w -> batch w
    float t = 0.f;
    for (int i = l; i < 256; i += 32) t += g_diffpart[w * 256 + i];
#pragma unroll
    for (int o = 16; o > 0; o >>= 1) t += __shfl_down_sync(0xffffffffu, t, o);
    __shared__ float sb[8];
    if (l == 0) sb[w] = sqrtf(t);
    __syncthreads();
    if (tid == 0) {
        float mm = 0.f;
#pragma unroll
        for (int bb = 0; bb < 8; bb++) mm += sb[bb];
        mm *= 0.125f;
        if (!(mm >= TOL)) g_converged = 1;   // NaN also stops (matches jax)
    }
}

// ---------------------------------------------------------------------------
extern "C" void kernel_launch(void* const* d_in, const int* in_sizes, int n_in,
                              void* d_out, int out_size)
{
    const float* inp     = (const float*)d_in[0];
    const float* core_w1 = (const float*)d_in[1];
    const float* core_b1 = (const float*)d_in[2];
    const float* gn_w    = (const float*)d_in[3];
    const float* gn_b    = (const float*)d_in[4];
    const float* core_w2 = (const float*)d_in[5];
    const float* core_b2 = (const float*)d_in[6];
    const float* stab_w1 = (const float*)d_in[7];
    const float* stab_b1 = (const float*)d_in[8];
    const float* stab_w2 = (const float*)d_in[9];
    const float* stab_b2 = (const float*)d_in[10];
    const float* fc1_w   = (const float*)d_in[11];
    const float* fc1_b   = (const float*)d_in[12];
    const float* fc2_w   = (const float*)d_in[13];
    const float* fc2_b   = (const float*)d_in[14];
    float* out = (float*)d_out;

    dim3 blk(16, 16);
    dim3 grd(16, 16, BATCH);

    // order chosen so conv1 is the 4th launch (ncu -s window lands on it)
    init_kernel<<<2048, 256>>>(inp);
    stab1_kernel<<<grd, blk>>>(inp, stab_w1, stab_b1);
    stab2_kernel<<<grd, blk>>>(stab_w2, stab_b2);
    conv1_kernel<<<grd, blk>>>(inp, core_w1, core_b1, gn_w, gn_b, 1);
    spec_kernel<<<BATCH, 1024>>>(inp, fc1_w, fc1_b, fc2_w, fc2_b);
    fused2_kernel<<<grd, blk>>>(inp, core_w2, core_b2, nullptr, 0);

    for (int it = 1; it < MAX_ITER; ++it) {
        conv1_kernel<<<grd, blk>>>(inp, core_w1, core_b1, gn_w, gn_b, 1);
        fused2_kernel<<<grd, blk>>>(inp, core_w2, core_b2, nullptr, 0);
    }
    // final core_f (always runs): z_star -> d_out
    conv1_kernel<<<grd, blk>>>(inp, core_w1, core_b1, gn_w, gn_b, 0);
    fused2_kernel<<<grd, blk>>>(inp, core_w2, core_b2, out, 1);
}

// round 5
// speedup vs baseline: 1.0670x; 1.0670x over previous
#include <cuda_runtime.h>
#include <cuda_bf16.h>
#include <math.h>

// ---------------------------------------------------------------------------
// MultiDEQPDEBlock: DEQ fixed-point PDE solver  (B=8, 256x256, hid=32, GN4)
// core_f: conv3x3(4->32) -> GN(4) -> GELU(erf) -> conv3x3(32->1) -> damped update
// Iteration diverges (|1-mask|>1 pixels) -> values ~1e37; all overflow paths
// mirror jax semantics (var->inf, rstd->0, xn->0; NaN diff stops loop).
// f32x2 packed FMA (FFMA2) throughout the conv inner loops.
// ---------------------------------------------------------------------------

#define BATCH 8
#define HH 256
#define WW 256
#define PIX (HH*WW)
#define HID 32
#define SHID 16
#define GROUPS 4
#define CPG 8
#define EPS 1e-5f
#define TOL 1e-4f
#define MAX_ITER 50
#define CFL_SCALE 0.015625f
#define NBLK_STAB 2048          // stab1 grid (16,16,8)
#define NBLK_C1   1024          // conv1 grid (8,16,8)
#define NBLK_F2   2048          // fused2 grid (16,16,8)

// ---- scratch (device globals; no cudaMalloc allowed) ----
__device__ float g_h[(size_t)BATCH*HID*PIX];      // 64 MB conv1 output (pre-GN)
__device__ float g_sh[(size_t)BATCH*SHID*PIX];    // 32 MB stabilizer hidden
__device__ float g_alpha[(size_t)BATCH*PIX];
__device__ float g_z[(size_t)BATCH*PIX];
__device__ float g_gamma[BATCH];
__device__ float g_part[BATCH*128*GROUPS*2];
__device__ float g_spart[BATCH*256*4];
__device__ float g_scale[BATCH*HID];
__device__ float g_shift[BATCH*HID];
__device__ float g_diffpart[BATCH*256];
__device__ int   g_converged;
__device__ unsigned g_cnt0;     // zero-init; self-resetting via atomicInc wrap
__device__ unsigned g_cnt1;
__device__ unsigned g_cnt2;

__device__ __forceinline__ float gelu_f(float x) {
    return 0.5f * x * (1.0f + erff(x * 0.70710678118654752f));
}
__device__ __forceinline__ float sigmoid_f(float x) {
    return 1.0f / (1.0f + expf(-x));
}

// ---- packed fp32x2 helpers (Blackwell FFMA2) ----
#define FMA2(acc, a, bb) asm("fma.rn.f32x2 %0, %1, %2, %0;" : "+l"(acc) : "l"(a), "l"(bb))
#define ADD2(acc, a)     asm("add.rn.f32x2 %0, %1, %0;"     : "+l"(acc) : "l"(a))
__device__ __forceinline__ unsigned long long pack2(float x) {
    unsigned long long r; asm("mov.b64 %0, {%1, %1};" : "=l"(r) : "f"(x)); return r;
}
#define UNPACK2(lo, hi, v) asm("mov.b64 {%0, %1}, %2;" : "=f"(lo), "=f"(hi) : "l"(v))

// ---------------------------------------------------------------------------
// stabilizer conv1 (3->16, GELU) + z init + spec partials; last block: gamma MLP
// ---------------------------------------------------------------------------
__global__ void __launch_bounds__(256) stab1_kernel(
    const float* __restrict__ inp, const float* __restrict__ w,
    const float* __restrict__ bias,
    const float* __restrict__ fc1_w, const float* __restrict__ fc1_b,
    const float* __restrict__ fc2_w, const float* __restrict__ fc2_b)
{
    const int b = blockIdx.z;
    const int tx0 = blockIdx.x * 16, ty0 = blockIdx.y * 16;
    __shared__ float s_in[3][18][18];
    __shared__ float s_w[27][16];
    __shared__ float s_b[16];
    __shared__ float s_red[8][4];
    __shared__ bool s_last;
    int tid = threadIdx.y * 16 + threadIdx.x;

    if (tid == 0 && blockIdx.x == 0 && blockIdx.y == 0 && b == 0) g_converged = 0;

    for (int i = tid; i < SHID * 27; i += 256) {
        int oc = i / 27, r = i % 27;
        s_w[r][oc] = w[i];
    }
    if (tid < SHID) s_b[tid] = bias[tid];

    const float* bp = inp + (size_t)b * 3 * PIX;
    for (int i = tid; i < 3 * 324; i += 256) {
        int c = i / 324, r = i % 324, yy = r / 18, xx = r % 18;
        int gy = ty0 + yy - 1, gx = tx0 + xx - 1;
        float v = 0.f;
        if ((unsigned)gy < 256u && (unsigned)gx < 256u)
            v = bp[c * PIX + gy * WW + gx];
        s_in[c][yy][xx] = v;
    }
    __syncthreads();

    int ty = threadIdx.y, tx = threadIdx.x;
    float in[27];
#pragma unroll
    for (int c = 0; c < 3; c++)
#pragma unroll
        for (int ky = 0; ky < 3; ky++)
#pragma unroll
            for (int kx = 0; kx < 3; kx++)
                in[c * 9 + ky * 3 + kx] = s_in[c][ty + ky][tx + kx];

    float acc[SHID];
#pragma unroll
    for (int oc = 0; oc < SHID; oc++) acc[oc] = s_b[oc];
#pragma unroll
    for (int r = 0; r < 27; r++) {
        float iv = in[r];
#pragma unroll
        for (int oc = 0; oc < SHID; oc++) acc[oc] += iv * s_w[r][oc];
    }

    int pix = (ty0 + ty) * WW + (tx0 + tx);
    float* out = g_sh + (size_t)b * SHID * PIX + pix;
#pragma unroll
    for (int oc = 0; oc < SHID; oc++)
        out[oc * PIX] = gelu_f(acc[oc]);

    // z init (channel 0 = boundary, center value is in s_in)
    g_z[b * PIX + pix] = s_in[0][ty + 1][tx + 1];

    // spec partials: |boundary| and k stats over the 16x16 interior
    float bv = fabsf(s_in[0][ty + 1][tx + 1]);
    float kv = s_in[2][ty + 1][tx + 1];
    float s1 = bv, q1 = bv * bv, s2 = kv, q2 = kv * kv;
#pragma unroll
    for (int o = 16; o > 0; o >>= 1) {
        s1 += __shfl_down_sync(0xffffffffu, s1, o);
        q1 += __shfl_down_sync(0xffffffffu, q1, o);
        s2 += __shfl_down_sync(0xffffffffu, s2, o);
        q2 += __shfl_down_sync(0xffffffffu, q2, o);
    }
    int lane = tid & 31, warp = tid >> 5;
    if (lane == 0) { s_red[warp][0] = s1; s_red[warp][1] = q1; s_red[warp][2] = s2; s_red[warp][3] = q2; }
    __syncthreads();
    int blin = blockIdx.y * 16 + blockIdx.x;
    if (tid < 4) {
        float v = 0.f;
#pragma unroll
        for (int w8 = 0; w8 < 8; w8++) v += s_red[w8][tid];
        g_spart[(b * 256 + blin) * 4 + tid] = v;
        __threadfence();
    }
    __syncthreads();
    if (tid == 0) {
        unsigned old = atomicInc(&g_cnt0, NBLK_STAB - 1u);
        s_last = (old == NBLK_STAB - 1u);
    }
    __syncthreads();
    if (!s_last) return;
    __threadfence();

    // last block: per-batch spec_ctrl MLP -> gamma (warp w = batch w)
    int w8 = tid >> 5, l = tid & 31;
    float S1 = 0, Q1 = 0, S2 = 0, Q2 = 0;
    for (int i = l; i < 256; i += 32) {
        S1 += g_spart[(w8 * 256 + i) * 4 + 0];
        Q1 += g_spart[(w8 * 256 + i) * 4 + 1];
        S2 += g_spart[(w8 * 256 + i) * 4 + 2];
        Q2 += g_spart[(w8 * 256 + i) * 4 + 3];
    }
#pragma unroll
    for (int o = 16; o > 0; o >>= 1) {
        S1 += __shfl_down_sync(0xffffffffu, S1, o);
        Q1 += __shfl_down_sync(0xffffffffu, Q1, o);
        S2 += __shfl_down_sync(0xffffffffu, S2, o);
        Q2 += __shfl_down_sync(0xffffffffu, Q2, o);
    }
    if (l == 0) {
        const float N = (float)PIX;
        float m1 = S1 / N, m2 = S2 / N;
        float v1 = (Q1 - N * m1 * m1) / (N - 1.0f);
        float v2 = (Q2 - N * m2 * m2) / (N - 1.0f);
        float feat[5] = { m1, sqrtf(fmaxf(v1, 0.f)), m2, sqrtf(fmaxf(v2, 0.f)), 1.0f };
        float outv = fc2_b[0];
        for (int j = 0; j < 32; j++) {
            float t = fc1_b[j];
#pragma unroll
            for (int i = 0; i < 5; i++) t += feat[i] * fc1_w[j * 5 + i];
            outv += gelu_f(t) * fc2_w[j];
        }
        g_gamma[w8] = (0.5f + 1.5f * sigmoid_f(outv)) * CFL_SCALE;
    }
}

// ---------------------------------------------------------------------------
// stabilizer conv2: 16->1, sigmoid -> alpha (one-time)
// ---------------------------------------------------------------------------
__global__ void __launch_bounds__(256) stab2_kernel(
    const float* __restrict__ w, const float* __restrict__ bias)
{
    const int b = blockIdx.z;
    const int tx0 = blockIdx.x * 16, ty0 = blockIdx.y * 16;
    __shared__ float s_in[SHID][18][18];
    __shared__ float s_w[SHID * 9];
    int tid = threadIdx.y * 16 + threadIdx.x;

    if (tid < SHID * 9) s_w[tid] = w[tid];
    const float* hp = g_sh + (size_t)b * SHID * PIX;
    for (int i = tid; i < SHID * 324; i += 256) {
        int c = i / 324, r = i % 324, yy = r / 18, xx = r % 18;
        int gy = ty0 + yy - 1, gx = tx0 + xx - 1;
        float v = 0.f;
        if ((unsigned)gy < 256u && (unsigned)gx < 256u)
            v = hp[c * PIX + gy * WW + gx];
        s_in[c][yy][xx] = v;
    }
    __syncthreads();

    int ty = threadIdx.y, tx = threadIdx.x;
    float acc = bias[0];
#pragma unroll
    for (int c = 0; c < SHID; c++)
#pragma unroll
        for (int ky = 0; ky < 3; ky++)
#pragma unroll
            for (int kx = 0; kx < 3; kx++)
                acc += s_w[c * 9 + ky * 3 + kx] * s_in[c][ty + ky][tx + kx];

    int pix = (ty0 + ty) * WW + (tx0 + tx);
    g_alpha[(size_t)b * PIX + pix] = sigmoid_f(acc);
}

// ---------------------------------------------------------------------------
// core conv1: [z,b,m,k](4)->32 via FFMA2 channel-pairs, 2 vertical px/thread.
// Block (32,8) -> tile 32x16. Writes g_h, GN partials; LAST BLOCK folds stats.
// ---------------------------------------------------------------------------
__global__ void __launch_bounds__(256, 2) conv1_kernel(
    const float* __restrict__ inp, const float* __restrict__ w1,
    const float* __restrict__ b1, const float* __restrict__ gn_w,
    const float* __restrict__ gn_b, int check)
{
    if (check && g_converged) return;
    const int b = blockIdx.z;
    const int tx0 = blockIdx.x * 32, ty0 = blockIdx.y * 16;
    __shared__ __align__(16) float s_in[4][18][34];
    __shared__ __align__(16) float s_w[36][32];
    __shared__ __align__(16) float s_b[32];
    __shared__ float s_red[8][8];
    __shared__ bool s_last;
    int tid = threadIdx.y * 32 + threadIdx.x;

    for (int i = tid; i < HID * 36; i += 256) {
        int oc = i / 36, r = i % 36;
        s_w[r][oc] = w1[i];
    }
    if (tid < HID) s_b[tid] = b1[tid];

    const float* zp = g_z + (size_t)b * PIX;
    const float* bp = inp + (size_t)b * 3 * PIX;
    for (int i = tid; i < 4 * 612; i += 256) {
        int c = i / 612, r = i % 612, yy = r / 34, xx = r % 34;
        int gy = ty0 + yy - 1, gx = tx0 + xx - 1;
        float v = 0.f;
        if ((unsigned)gy < 256u && (unsigned)gx < 256u) {
            int off = gy * WW + gx;
            v = (c == 0) ? zp[off] : bp[(c - 1) * PIX + off];
        }
        s_in[c][yy][xx] = v;
    }
    __syncthreads();

    const int tx = threadIdx.x;
    const int ty2 = threadIdx.y * 2;       // pixel rows ty2, ty2+1

    unsigned long long acc0[16], acc1[16];
#pragma unroll
    for (int j = 0; j < 16; j++) {
        acc0[j] = ((const unsigned long long*)s_b)[j];
        acc1[j] = acc0[j];
    }

#pragma unroll
    for (int c = 0; c < 4; c++) {
#pragma unroll
        for (int kx = 0; kx < 3; kx++) {
            float v0 = s_in[c][ty2 + 0][tx + kx];
            float v1 = s_in[c][ty2 + 1][tx + kx];
            float v2 = s_in[c][ty2 + 2][tx + kx];
            float v3 = s_in[c][ty2 + 3][tx + kx];
            unsigned long long p0 = pack2(v0), p1 = pack2(v1);
            unsigned long long p2 = pack2(v2), p3 = pack2(v3);
#pragma unroll
            for (int ky = 0; ky < 3; ky++) {
                int r = c * 9 + ky * 3 + kx;
                unsigned long long s0 = (ky == 0) ? p0 : ((ky == 1) ? p1 : p2);
                unsigned long long s1 = (ky == 0) ? p1 : ((ky == 1) ? p2 : p3);
                const ulonglong2* wrow = (const ulonglong2*)&s_w[r][0];
#pragma unroll
                for (int j4 = 0; j4 < 8; j4++) {
                    ulonglong2 wp = wrow[j4];
                    FMA2(acc0[2 * j4 + 0], s0, wp.x);
                    FMA2(acc0[2 * j4 + 1], s0, wp.y);
                    FMA2(acc1[2 * j4 + 0], s1, wp.x);
                    FMA2(acc1[2 * j4 + 1], s1, wp.y);
                }
            }
        }
    }

    // GN partial sums (packed), h stores
    unsigned long long gs2[4], gq2[4];
#pragma unroll
    for (int g = 0; g < 4; g++) { gs2[g] = 0ull; gq2[g] = 0ull; }
#pragma unroll
    for (int j = 0; j < 16; j++) {
        int g = j >> 2;                       // pair (2j,2j+1) -> group (2j)>>3
        ADD2(gs2[g], acc0[j]);
        ADD2(gs2[g], acc1[j]);
        FMA2(gq2[g], acc0[j], acc0[j]);
        FMA2(gq2[g], acc1[j], acc1[j]);
    }
    {
        int gy0 = ty0 + ty2, gx = tx0 + tx;
        float* hp = g_h + (size_t)b * HID * PIX + gy0 * WW + gx;
#pragma unroll
        for (int j = 0; j < 16; j++) {
            float f0, f1;
            UNPACK2(f0, f1, acc0[j]);
            hp[(2 * j) * PIX] = f0;
            hp[(2 * j + 1) * PIX] = f1;
            UNPACK2(f0, f1, acc1[j]);
            hp[(2 * j) * PIX + WW] = f0;
            hp[(2 * j + 1) * PIX + WW] = f1;
        }
    }

#pragma unroll
    for (int o = 16; o > 0; o >>= 1) {
#pragma unroll
        for (int g = 0; g < 4; g++) {
            unsigned long long t;
            t = __shfl_down_sync(0xffffffffu, gs2[g], o); ADD2(gs2[g], t);
            t = __shfl_down_sync(0xffffffffu, gq2[g], o); ADD2(gq2[g], t);
        }
    }
    int lane = tid & 31, warp = tid >> 5;
    if (lane == 0) {
#pragma unroll
        for (int g = 0; g < 4; g++) {
            float lo, hi;
            UNPACK2(lo, hi, gs2[g]); s_red[warp][g] = lo + hi;
            UNPACK2(lo, hi, gq2[g]); s_red[warp][4 + g] = lo + hi;
        }
    }
    __syncthreads();
    int blin = blockIdx.y * 8 + blockIdx.x;   // gridDim.x = 8
    if (tid < 8) {
        float v = 0.f;
#pragma unroll
        for (int w = 0; w < 8; w++) v += s_red[w][tid];
        int g = tid & 3, which = tid >> 2;
        g_part[((b * 128 + blin) * 4 + g) * 2 + which] = v;
        __threadfence();
    }
    __syncthreads();
    if (tid == 0) {
        unsigned old = atomicInc(&g_cnt1, NBLK_C1 - 1u);
        s_last = (old == NBLK_C1 - 1u);
    }
    __syncthreads();
    if (!s_last) return;
    __threadfence();

    // last block: fold GN stats for all 32 (b,g) pairs; 8 lanes per pair
    int pair = tid >> 3, l8 = tid & 7;        // pair = bb*4 + g
    int bb = pair >> 2, g = pair & 3;
    float s = 0.f, q = 0.f;
    for (int i = l8; i < 128; i += 8) {
        s += g_part[((bb * 128 + i) * 4 + g) * 2 + 0];
        q += g_part[((bb * 128 + i) * 4 + g) * 2 + 1];
    }
#pragma unroll
    for (int o = 4; o > 0; o >>= 1) {
        s += __shfl_down_sync(0xffffffffu, s, o, 8);
        q += __shfl_down_sync(0xffffffffu, q, o, 8);
    }
    if (l8 == 0) {
        const float invN = 1.0f / (float)(CPG * PIX);
        float mean = s * invN;
        float Qn = q * invN;
        float var = isinf(Qn) ? Qn : fmaxf(Qn - mean * mean, 0.0f);
        float rstd = rsqrtf(var + EPS);       // var=inf -> rstd=0
#pragma unroll
        for (int c = 0; c < CPG; c++) {
            int gc = g * CPG + c;
            float sc = gn_w[gc] * rstd;
            g_scale[bb * HID + gc] = sc;
            g_shift[bb * HID + gc] = (rstd == 0.0f) ? gn_b[gc] : (gn_b[gc] - mean * sc);
        }
    }
}

// ---------------------------------------------------------------------------
// fused2: GN->GELU->conv2(32->1) via FFMA2 channel-pairs -> damped update.
// s_h layout [pixel(18x18)][36 (32 ch + pad)]. LAST BLOCK folds diff.
// ---------------------------------------------------------------------------
__global__ void __launch_bounds__(256) fused2_kernel(
    const float* __restrict__ inp, const float* __restrict__ w2,
    const float* __restrict__ b2, float* __restrict__ final_out, int mode)
{
    if (mode == 0 && g_converged) return;
    const int b = blockIdx.z;
    const int tx0 = blockIdx.x * 16, ty0 = blockIdx.y * 16;
    __shared__ __align__(16) float s_h[324 * 36];
    __shared__ __align__(16) float s_wt[9 * 32];   // [pos][ch]
    __shared__ float s_sc[HID], s_sf[HID];
    __shared__ float s_red[8];
    __shared__ bool s_last;
    int tid = threadIdx.y * 16 + threadIdx.x;

    for (int i = tid; i < HID * 9; i += 256) {
        int c = i / 9, pos = i % 9;
        s_wt[pos * 32 + c] = w2[i];
    }
    if (tid < HID) { s_sc[tid] = g_scale[b * HID + tid]; s_sf[tid] = g_shift[b * HID + tid]; }
    __syncthreads();

    const float* hp = g_h + (size_t)b * HID * PIX;
    for (int p = tid; p < 324; p += 256) {
        int yy = p / 18, xx = p % 18;
        int gy = ty0 + yy - 1, gx = tx0 + xx - 1;
        bool inb = ((unsigned)gy < 256u) && ((unsigned)gx < 256u);
        int goff = gy * WW + gx;
        float4* dst = (float4*)&s_h[p * 36];
#pragma unroll
        for (int c4 = 0; c4 < 8; c4++) {
            float4 v = make_float4(0.f, 0.f, 0.f, 0.f);
            if (inb) {
                float r[4];
#pragma unroll
                for (int e = 0; e < 4; e++) {
                    int c = c4 * 4 + e;
                    float hv = hp[c * PIX + goff];
                    float sc = s_sc[c];
                    // sc==0 <=> overflow regime (hv may be inf); ref gives gn_b
                    float t = (sc == 0.0f) ? s_sf[c] : (hv * sc + s_sf[c]);
                    r[e] = gelu_f(t);
                }
                v = make_float4(r[0], r[1], r[2], r[3]);
            }
            dst[c4] = v;
        }
    }
    __syncthreads();

    int ty = threadIdx.y, tx = threadIdx.x;
    unsigned long long pa0 = 0ull, pa1 = 0ull;    // (ch%4==0,1) and (ch%4==2,3)
#pragma unroll
    for (int ky = 0; ky < 3; ky++)
#pragma unroll
        for (int kx = 0; kx < 3; kx++) {
            const ulonglong2* h2 = (const ulonglong2*)&s_h[((ty + ky) * 18 + tx + kx) * 36];
            const ulonglong2* w2p = (const ulonglong2*)&s_wt[(ky * 3 + kx) * 32];
#pragma unroll
            for (int c4 = 0; c4 < 8; c4++) {
                ulonglong2 h = h2[c4], w = w2p[c4];
                FMA2(pa0, h.x, w.x);
                FMA2(pa1, h.y, w.y);
            }
        }
    float a0, a1, a2, a3;
    UNPACK2(a0, a1, pa0);
    UNPACK2(a2, a3, pa1);
    float acc = b2[0] + ((a0 + a1) + (a2 + a3));

    int pix = (ty0 + ty) * WW + (tx0 + tx);
    int off = b * PIX + pix;
    const float* bp = inp + (size_t)b * 3 * PIX;
    float zold = g_z[off];
    // mirror XLA elementwise rounding exactly (no FMA contraction)
    float ga   = __fmul_rn(g_gamma[b], g_alpha[off]);
    float znew = __fadd_rn(zold, __fmul_rn(ga, acc));
    float m  = bp[PIX + pix];
    float bv = bp[pix];
    float res = __fadd_rn(__fmul_rn(znew, __fadd_rn(1.0f, -m)), __fmul_rn(bv, m));

    if (mode != 0) { final_out[off] = res; return; }

    g_z[off] = res;
    float d = __fadd_rn(res, -zold);
    float s = d * d;
#pragma unroll
    for (int o = 16; o > 0; o >>= 1) s += __shfl_down_sync(0xffffffffu, s, o);
    int lane = tid & 31, warp = tid >> 5;
    if (lane == 0) s_red[warp] = s;
    __syncthreads();
    int blin = blockIdx.y * 16 + blockIdx.x;
    if (tid == 0) {
        float t = 0.f;
#pragma unroll
        for (int w = 0; w < 8; w++) t += s_red[w];
        g_diffpart[b * 256 + blin] = t;
        __threadfence();
        unsigned old = atomicInc(&g_cnt2, NBLK_F2 - 1u);
        s_last = (old == NBLK_F2 - 1u);
    }
    __syncthreads();
    if (!s_last) return;
    __threadfence();

    // last block: diff = mean_b ||dz_b||; jax cond continues while diff>=TOL
    int w = tid >> 5, l = tid & 31;
    float t = 0.f;
    for (int i = l; i < 256; i += 32) t += g_diffpart[w * 256 + i];
#pragma unroll
    for (int o = 16; o > 0; o >>= 1) t += __shfl_down_sync(0xffffffffu, t, o);
    __shared__ float sb[8];
    if (l == 0) sb[w] = sqrtf(t);
    __syncthreads();
    if (tid == 0) {
        float mm = 0.f;
#pragma unroll
        for (int bb = 0; bb < 8; bb++) mm += sb[bb];
        mm *= 0.125f;
        if (!(mm >= TOL)) g_converged = 1;   // NaN also stops (matches jax)
    }
}

// ---------------------------------------------------------------------------
extern "C" void kernel_launch(void* const* d_in, const int* in_sizes, int n_in,
                              void* d_out, int out_size)
{
    const float* inp     = (const float*)d_in[0];
    const float* core_w1 = (const float*)d_in[1];
    const float* core_b1 = (const float*)d_in[2];
    const float* gn_w    = (const float*)d_in[3];
    const float* gn_b    = (const float*)d_in[4];
    const float* core_w2 = (const float*)d_in[5];
    const float* core_b2 = (const float*)d_in[6];
    const float* stab_w1 = (const float*)d_in[7];
    const float* stab_b1 = (const float*)d_in[8];
    const float* stab_w2 = (const float*)d_in[9];
    const float* stab_b2 = (const float*)d_in[10];
    const float* fc1_w   = (const float*)d_in[11];
    const float* fc1_b   = (const float*)d_in[12];
    const float* fc2_w   = (const float*)d_in[13];
    const float* fc2_b   = (const float*)d_in[14];
    float* out = (float*)d_out;

    dim3 blk16(16, 16);
    dim3 grd16(16, 16, BATCH);
    dim3 blkC1(32, 8);
    dim3 grdC1(8, 16, BATCH);

    // stab1 folds in z-init + spec_ctrl(gamma); fused2 is 4th launch for ncu
    stab1_kernel<<<grd16, blk16>>>(inp, stab_w1, stab_b1, fc1_w, fc1_b, fc2_w, fc2_b);
    stab2_kernel<<<grd16, blk16>>>(stab_w2, stab_b2);
    conv1_kernel<<<grdC1, blkC1>>>(inp, core_w1, core_b1, gn_w, gn_b, 1);
    fused2_kernel<<<grd16, blk16>>>(inp, core_w2, core_b2, nullptr, 0);

    for (int it = 1; it < MAX_ITER; ++it) {
        conv1_kernel<<<grdC1, blkC1>>>(inp, core_w1, core_b1, gn_w, gn_b, 1);
        fused2_kernel<<<grd16, blk16>>>(inp, core_w2, core_b2, nullptr, 0);
    }
    // final core_f (always runs): z_star -> d_out
    conv1_kernel<<<grdC1, blkC1>>>(inp, core_w1, core_b1, gn_w, gn_b, 0);
    fused2_kernel<<<grd16, blk16>>>(inp, core_w2, core_b2, out, 1);
}

// round 6
// speedup vs baseline: 1.2648x; 1.1854x over previous
#include <cuda_runtime.h>
#include <cuda_bf16.h>
#include <math.h>

// ---------------------------------------------------------------------------
// MultiDEQPDEBlock: DEQ fixed-point PDE solver  (B=8, 256x256, hid=32, GN4)
// core_f: conv3x3(4->32) -> GN(4) -> GELU(erf) -> conv3x3(32->1) -> damped update
// Key trick: channels [b,m,k] are loop-invariant -> h_fixed precomputed once;
// per-iter conv1 is only the 9-tap z convolution (4x FLOP cut).
// Divergent dynamics (|1-mask|>1) push values to ~1e37: all overflow paths
// mirror jax semantics (var->inf, rstd->0, xn->0; NaN diff stops loop).
// ---------------------------------------------------------------------------

#define BATCH 8
#define HH 256
#define WW 256
#define PIX (HH*WW)
#define HID 32
#define SHID 16
#define GROUPS 4
#define CPG 8
#define EPS 1e-5f
#define TOL 1e-4f
#define MAX_ITER 50
#define CFL_SCALE 0.015625f
#define NBLK 2048               // (16,16,8) grids

// ---- scratch (device globals; no cudaMalloc allowed) ----
__device__ float g_h[(size_t)BATCH*HID*PIX];      // 64 MB conv1 output (pre-GN)
__device__ float g_hfix[(size_t)BATCH*HID*PIX];   // 64 MB conv of fixed channels
__device__ float g_sh[(size_t)BATCH*SHID*PIX];    // 32 MB stabilizer hidden
__device__ float g_alpha[(size_t)BATCH*PIX];
__device__ float g_z[(size_t)BATCH*PIX];
__device__ float g_gamma[BATCH];
__device__ float g_part[BATCH*256*GROUPS*2];
__device__ float g_spart[BATCH*256*4];
__device__ float g_scale[BATCH*HID];
__device__ float g_shift[BATCH*HID];
__device__ float g_diffpart[BATCH*256];
__device__ int   g_converged;
__device__ unsigned g_cnt0;     // zero-init; self-resetting via atomicInc wrap
__device__ unsigned g_cnt1;
__device__ unsigned g_cnt2;

__device__ __forceinline__ float gelu_f(float x) {
    return 0.5f * x * (1.0f + erff(x * 0.70710678118654752f));
}
__device__ __forceinline__ float sigmoid_f(float x) {
    return 1.0f / (1.0f + expf(-x));
}

// ---------------------------------------------------------------------------
// stabilizer conv1 (3->16, GELU) + z init + spec partials; last block: gamma MLP
// ---------------------------------------------------------------------------
__global__ void __launch_bounds__(256) stab1_kernel(
    const float* __restrict__ inp, const float* __restrict__ w,
    const float* __restrict__ bias,
    const float* __restrict__ fc1_w, const float* __restrict__ fc1_b,
    const float* __restrict__ fc2_w, const float* __restrict__ fc2_b)
{
    const int b = blockIdx.z;
    const int tx0 = blockIdx.x * 16, ty0 = blockIdx.y * 16;
    __shared__ float s_in[3][18][18];
    __shared__ float s_w[27][16];
    __shared__ float s_b[16];
    __shared__ float s_red[8][4];
    __shared__ bool s_last;
    int tid = threadIdx.y * 16 + threadIdx.x;

    if (tid == 0 && blockIdx.x == 0 && blockIdx.y == 0 && b == 0) g_converged = 0;

    for (int i = tid; i < SHID * 27; i += 256) {
        int oc = i / 27, r = i % 27;
        s_w[r][oc] = w[i];
    }
    if (tid < SHID) s_b[tid] = bias[tid];

    const float* bp = inp + (size_t)b * 3 * PIX;
    for (int i = tid; i < 3 * 324; i += 256) {
        int c = i / 324, r = i % 324, yy = r / 18, xx = r % 18;
        int gy = ty0 + yy - 1, gx = tx0 + xx - 1;
        float v = 0.f;
        if ((unsigned)gy < 256u && (unsigned)gx < 256u)
            v = bp[c * PIX + gy * WW + gx];
        s_in[c][yy][xx] = v;
    }
    __syncthreads();

    int ty = threadIdx.y, tx = threadIdx.x;
    float in[27];
#pragma unroll
    for (int c = 0; c < 3; c++)
#pragma unroll
        for (int ky = 0; ky < 3; ky++)
#pragma unroll
            for (int kx = 0; kx < 3; kx++)
                in[c * 9 + ky * 3 + kx] = s_in[c][ty + ky][tx + kx];

    float acc[SHID];
#pragma unroll
    for (int oc = 0; oc < SHID; oc++) acc[oc] = s_b[oc];
#pragma unroll
    for (int r = 0; r < 27; r++) {
        float iv = in[r];
#pragma unroll
        for (int oc = 0; oc < SHID; oc++) acc[oc] += iv * s_w[r][oc];
    }

    int pix = (ty0 + ty) * WW + (tx0 + tx);
    float* out = g_sh + (size_t)b * SHID * PIX + pix;
#pragma unroll
    for (int oc = 0; oc < SHID; oc++)
        out[oc * PIX] = gelu_f(acc[oc]);

    // z init (channel 0 = boundary, center value is in s_in)
    g_z[b * PIX + pix] = s_in[0][ty + 1][tx + 1];

    // spec partials: |boundary| and k stats
    float bv = fabsf(s_in[0][ty + 1][tx + 1]);
    float kv = s_in[2][ty + 1][tx + 1];
    float s1 = bv, q1 = bv * bv, s2 = kv, q2 = kv * kv;
#pragma unroll
    for (int o = 16; o > 0; o >>= 1) {
        s1 += __shfl_down_sync(0xffffffffu, s1, o);
        q1 += __shfl_down_sync(0xffffffffu, q1, o);
        s2 += __shfl_down_sync(0xffffffffu, s2, o);
        q2 += __shfl_down_sync(0xffffffffu, q2, o);
    }
    int lane = tid & 31, warp = tid >> 5;
    if (lane == 0) { s_red[warp][0] = s1; s_red[warp][1] = q1; s_red[warp][2] = s2; s_red[warp][3] = q2; }
    __syncthreads();
    int blin = blockIdx.y * 16 + blockIdx.x;
    if (tid < 4) {
        float v = 0.f;
#pragma unroll
        for (int w8 = 0; w8 < 8; w8++) v += s_red[w8][tid];
        g_spart[(b * 256 + blin) * 4 + tid] = v;
        __threadfence();
    }
    __syncthreads();
    if (tid == 0) {
        unsigned old = atomicInc(&g_cnt0, NBLK - 1u);
        s_last = (old == NBLK - 1u);
    }
    __syncthreads();
    if (!s_last) return;
    __threadfence();

    // last block: per-batch spec_ctrl MLP -> gamma (warp w = batch w)
    int w8 = tid >> 5, l = tid & 31;
    float S1 = 0, Q1 = 0, S2 = 0, Q2 = 0;
    for (int i = l; i < 256; i += 32) {
        S1 += g_spart[(w8 * 256 + i) * 4 + 0];
        Q1 += g_spart[(w8 * 256 + i) * 4 + 1];
        S2 += g_spart[(w8 * 256 + i) * 4 + 2];
        Q2 += g_spart[(w8 * 256 + i) * 4 + 3];
    }
#pragma unroll
    for (int o = 16; o > 0; o >>= 1) {
        S1 += __shfl_down_sync(0xffffffffu, S1, o);
        Q1 += __shfl_down_sync(0xffffffffu, Q1, o);
        S2 += __shfl_down_sync(0xffffffffu, S2, o);
        Q2 += __shfl_down_sync(0xffffffffu, Q2, o);
    }
    if (l == 0) {
        const float N = (float)PIX;
        float m1 = S1 / N, m2 = S2 / N;
        float v1 = (Q1 - N * m1 * m1) / (N - 1.0f);
        float v2 = (Q2 - N * m2 * m2) / (N - 1.0f);
        float feat[5] = { m1, sqrtf(fmaxf(v1, 0.f)), m2, sqrtf(fmaxf(v2, 0.f)), 1.0f };
        float outv = fc2_b[0];
        for (int j = 0; j < 32; j++) {
            float t = fc1_b[j];
#pragma unroll
            for (int i = 0; i < 5; i++) t += feat[i] * fc1_w[j * 5 + i];
            outv += gelu_f(t) * fc2_w[j];
        }
        g_gamma[w8] = (0.5f + 1.5f * sigmoid_f(outv)) * CFL_SCALE;
    }
}

// ---------------------------------------------------------------------------
// stabilizer conv2: 16->1, sigmoid -> alpha (one-time)
// ---------------------------------------------------------------------------
__global__ void __launch_bounds__(256) stab2_kernel(
    const float* __restrict__ w, const float* __restrict__ bias)
{
    const int b = blockIdx.z;
    const int tx0 = blockIdx.x * 16, ty0 = blockIdx.y * 16;
    __shared__ float s_in[SHID][18][18];
    __shared__ float s_w[SHID * 9];
    int tid = threadIdx.y * 16 + threadIdx.x;

    if (tid < SHID * 9) s_w[tid] = w[tid];
    const float* hp = g_sh + (size_t)b * SHID * PIX;
    for (int i = tid; i < SHID * 324; i += 256) {
        int c = i / 324, r = i % 324, yy = r / 18, xx = r % 18;
        int gy = ty0 + yy - 1, gx = tx0 + xx - 1;
        float v = 0.f;
        if ((unsigned)gy < 256u && (unsigned)gx < 256u)
            v = hp[c * PIX + gy * WW + gx];
        s_in[c][yy][xx] = v;
    }
    __syncthreads();

    int ty = threadIdx.y, tx = threadIdx.x;
    float acc = bias[0];
#pragma unroll
    for (int c = 0; c < SHID; c++)
#pragma unroll
        for (int ky = 0; ky < 3; ky++)
#pragma unroll
            for (int kx = 0; kx < 3; kx++)
                acc += s_w[c * 9 + ky * 3 + kx] * s_in[c][ty + ky][tx + kx];

    int pix = (ty0 + ty) * WW + (tx0 + tx);
    g_alpha[(size_t)b * PIX + pix] = sigmoid_f(acc);
}

// ---------------------------------------------------------------------------
// hfix: one-time conv3x3 of fixed channels [b,m,k] (w1[:,1:4]) + bias -> g_hfix
// ---------------------------------------------------------------------------
__global__ void __launch_bounds__(256) hfix_kernel(
    const float* __restrict__ inp, const float* __restrict__ w1,
    const float* __restrict__ b1)
{
    const int b = blockIdx.z;
    const int tx0 = blockIdx.x * 16, ty0 = blockIdx.y * 16;
    __shared__ float s_in[3][18][18];
    __shared__ __align__(16) float s_w[27][32];
    __shared__ float s_b[32];
    int tid = threadIdx.y * 16 + threadIdx.x;

    for (int i = tid; i < HID * 27; i += 256) {
        int oc = i / 27, r = i % 27;
        s_w[r][oc] = w1[oc * 36 + 9 + r];   // skip z-channel taps (c=0)
    }
    if (tid < HID) s_b[tid] = b1[tid];

    const float* bp = inp + (size_t)b * 3 * PIX;
    for (int i = tid; i < 3 * 324; i += 256) {
        int c = i / 324, r = i % 324, yy = r / 18, xx = r % 18;
        int gy = ty0 + yy - 1, gx = tx0 + xx - 1;
        float v = 0.f;
        if ((unsigned)gy < 256u && (unsigned)gx < 256u)
            v = bp[c * PIX + gy * WW + gx];
        s_in[c][yy][xx] = v;
    }
    __syncthreads();

    int ty = threadIdx.y, tx = threadIdx.x;
    float acc[HID];
#pragma unroll
    for (int oc = 0; oc < HID; oc++) acc[oc] = s_b[oc];
#pragma unroll
    for (int c = 0; c < 3; c++)
#pragma unroll
        for (int ky = 0; ky < 3; ky++)
#pragma unroll
            for (int kx = 0; kx < 3; kx++) {
                float iv = s_in[c][ty + ky][tx + kx];
                int r = c * 9 + ky * 3 + kx;
#pragma unroll
                for (int j = 0; j < 8; j++) {
                    float4 w4 = ((const float4*)&s_w[r][0])[j];
                    acc[4*j+0] += iv * w4.x; acc[4*j+1] += iv * w4.y;
                    acc[4*j+2] += iv * w4.z; acc[4*j+3] += iv * w4.w;
                }
            }

    int pix = (ty0 + ty) * WW + (tx0 + tx);
    float* hp = g_hfix + (size_t)b * HID * PIX + pix;
#pragma unroll
    for (int oc = 0; oc < HID; oc++) hp[oc * PIX] = acc[oc];
}

// ---------------------------------------------------------------------------
// convz: h = h_fixed + conv3x3(z, w1[:,0])  (9 taps), write g_h + GN partials;
// LAST BLOCK folds GN stats -> scale/shift.
// ---------------------------------------------------------------------------
__global__ void __launch_bounds__(256, 4) convz_kernel(
    const float* __restrict__ w1, const float* __restrict__ gn_w,
    const float* __restrict__ gn_b, int check)
{
    if (check && g_converged) return;
    const int b = blockIdx.z;
    const int tx0 = blockIdx.x * 16, ty0 = blockIdx.y * 16;
    __shared__ float s_z[18][18];
    __shared__ __align__(16) float s_w[9][32];
    __shared__ float s_red[8][8];
    __shared__ bool s_last;
    int tid = threadIdx.y * 16 + threadIdx.x;

    for (int i = tid; i < HID * 9; i += 256) {
        int oc = i / 9, r = i % 9;
        s_w[r][oc] = w1[oc * 36 + r];       // z-channel taps (c=0)
    }

    const float* zp = g_z + (size_t)b * PIX;
    for (int i = tid; i < 324; i += 256) {
        int yy = i / 18, xx = i % 18;
        int gy = ty0 + yy - 1, gx = tx0 + xx - 1;
        float v = 0.f;
        if ((unsigned)gy < 256u && (unsigned)gx < 256u)
            v = zp[gy * WW + gx];
        s_z[yy][xx] = v;
    }
    __syncthreads();

    int ty = threadIdx.y, tx = threadIdx.x;
    float zv[9];
#pragma unroll
    for (int ky = 0; ky < 3; ky++)
#pragma unroll
        for (int kx = 0; kx < 3; kx++)
            zv[ky * 3 + kx] = s_z[ty + ky][tx + kx];

    int pix = (ty0 + ty) * WW + (tx0 + tx);
    const float* fp = g_hfix + (size_t)b * HID * PIX + pix;
    float acc[HID];
#pragma unroll
    for (int oc = 0; oc < HID; oc++) acc[oc] = fp[oc * PIX];
#pragma unroll
    for (int r = 0; r < 9; r++) {
        float iv = zv[r];
#pragma unroll
        for (int j = 0; j < 8; j++) {
            float4 w4 = ((const float4*)&s_w[r][0])[j];
            acc[4*j+0] += iv * w4.x; acc[4*j+1] += iv * w4.y;
            acc[4*j+2] += iv * w4.z; acc[4*j+3] += iv * w4.w;
        }
    }

    float* hp = g_h + (size_t)b * HID * PIX + pix;
    float gs[4] = {0, 0, 0, 0}, gq[4] = {0, 0, 0, 0};
#pragma unroll
    for (int oc = 0; oc < HID; oc++) {
        float v = acc[oc];
        hp[oc * PIX] = v;
        gs[oc >> 3] += v;
        gq[oc >> 3] += v * v;
    }
#pragma unroll
    for (int o = 16; o > 0; o >>= 1) {
#pragma unroll
        for (int g = 0; g < 4; g++) {
            gs[g] += __shfl_down_sync(0xffffffffu, gs[g], o);
            gq[g] += __shfl_down_sync(0xffffffffu, gq[g], o);
        }
    }
    int lane = tid & 31, warp = tid >> 5;
    if (lane == 0) {
#pragma unroll
        for (int g = 0; g < 4; g++) { s_red[warp][g] = gs[g]; s_red[warp][4 + g] = gq[g]; }
    }
    __syncthreads();
    int blin = blockIdx.y * 16 + blockIdx.x;
    if (tid < 8) {
        float v = 0.f;
#pragma unroll
        for (int w = 0; w < 8; w++) v += s_red[w][tid];
        int g = tid & 3, which = tid >> 2;
        g_part[((b * 256 + blin) * 4 + g) * 2 + which] = v;
        __threadfence();
    }
    __syncthreads();
    if (tid == 0) {
        unsigned old = atomicInc(&g_cnt1, NBLK - 1u);
        s_last = (old == NBLK - 1u);
    }
    __syncthreads();
    if (!s_last) return;
    __threadfence();

    // last block: fold GN stats for all 32 (b,g) pairs; 8 lanes per pair
    int pair = tid >> 3, l8 = tid & 7;
    int bb = pair >> 2, g = pair & 3;
    float s = 0.f, q = 0.f;
    for (int i = l8; i < 256; i += 8) {
        s += g_part[((bb * 256 + i) * 4 + g) * 2 + 0];
        q += g_part[((bb * 256 + i) * 4 + g) * 2 + 1];
    }
#pragma unroll
    for (int o = 4; o > 0; o >>= 1) {
        s += __shfl_down_sync(0xffffffffu, s, o, 8);
        q += __shfl_down_sync(0xffffffffu, q, o, 8);
    }
    if (l8 == 0) {
        const float invN = 1.0f / (float)(CPG * PIX);
        float mean = s * invN;
        float Qn = q * invN;
        float var = isinf(Qn) ? Qn : fmaxf(Qn - mean * mean, 0.0f);
        float rstd = rsqrtf(var + EPS);       // var=inf -> rstd=0
#pragma unroll
        for (int c = 0; c < CPG; c++) {
            int gc = g * CPG + c;
            float sc = gn_w[gc] * rstd;
            g_scale[bb * HID + gc] = sc;
            g_shift[bb * HID + gc] = (rstd == 0.0f) ? gn_b[gc] : (gn_b[gc] - mean * sc);
        }
    }
}

// ---------------------------------------------------------------------------
// fused2 (r3-proven structure): GN->GELU->conv2(32->1)->damped update.
// LAST BLOCK folds diff and sets convergence flag.
// ---------------------------------------------------------------------------
__global__ void __launch_bounds__(256) fused2_kernel(
    const float* __restrict__ inp, const float* __restrict__ w2,
    const float* __restrict__ b2, float* __restrict__ final_out, int mode)
{
    if (mode == 0 && g_converged) return;
    const int b = blockIdx.z;
    const int tx0 = blockIdx.x * 16, ty0 = blockIdx.y * 16;
    __shared__ float s_h[HID][18][18];
    __shared__ float s_w[HID * 9];
    __shared__ float s_sc[HID], s_sf[HID];
    __shared__ float s_red[8];
    __shared__ bool s_last;
    int tid = threadIdx.y * 16 + threadIdx.x;

    for (int i = tid; i < HID * 9; i += 256) s_w[i] = w2[i];
    if (tid < HID) { s_sc[tid] = g_scale[b * HID + tid]; s_sf[tid] = g_shift[b * HID + tid]; }
    __syncthreads();

    const float* hp = g_h + (size_t)b * HID * PIX;
    for (int i = tid; i < HID * 324; i += 256) {
        int c = i / 324, r = i % 324, yy = r / 18, xx = r % 18;
        int gy = ty0 + yy - 1, gx = tx0 + xx - 1;
        float v = 0.f;
        if ((unsigned)gy < 256u && (unsigned)gx < 256u) {
            float hv = hp[c * PIX + gy * WW + gx];
            float sc = s_sc[c];
            // sc==0 <=> overflow regime (hv may be inf); ref gives gn_b
            float t = (sc == 0.0f) ? s_sf[c] : (hv * sc + s_sf[c]);
            v = gelu_f(t);
        }
        s_h[c][yy][xx] = v;
    }
    __syncthreads();

    int ty = threadIdx.y, tx = threadIdx.x;
    float acc = b2[0];
#pragma unroll
    for (int c = 0; c < HID; c++)
#pragma unroll
        for (int ky = 0; ky < 3; ky++)
#pragma unroll
            for (int kx = 0; kx < 3; kx++)
                acc += s_w[c * 9 + ky * 3 + kx] * s_h[c][ty + ky][tx + kx];

    int pix = (ty0 + ty) * WW + (tx0 + tx);
    int off = b * PIX + pix;
    const float* bp = inp + (size_t)b * 3 * PIX;
    float zold = g_z[off];
    // mirror XLA elementwise rounding exactly (no FMA contraction)
    float ga   = __fmul_rn(g_gamma[b], g_alpha[off]);
    float znew = __fadd_rn(zold, __fmul_rn(ga, acc));
    float m  = bp[PIX + pix];
    float bv = bp[pix];
    float res = __fadd_rn(__fmul_rn(znew, __fadd_rn(1.0f, -m)), __fmul_rn(bv, m));

    if (mode != 0) { final_out[off] = res; return; }

    g_z[off] = res;
    float d = __fadd_rn(res, -zold);
    float s = d * d;
#pragma unroll
    for (int o = 16; o > 0; o >>= 1) s += __shfl_down_sync(0xffffffffu, s, o);
    int lane = tid & 31, warp = tid >> 5;
    if (lane == 0) s_red[warp] = s;
    __syncthreads();
    int blin = blockIdx.y * 16 + blockIdx.x;
    if (tid == 0) {
        float t = 0.f;
#pragma unroll
        for (int w = 0; w < 8; w++) t += s_red[w];
        g_diffpart[b * 256 + blin] = t;
        __threadfence();
        unsigned old = atomicInc(&g_cnt2, NBLK - 1u);
        s_last = (old == NBLK - 1u);
    }
    __syncthreads();
    if (!s_last) return;
    __threadfence();

    // last block: diff = mean_b ||dz_b||; jax cond continues while diff>=TOL
    int w = tid >> 5, l = tid & 31;
    float t = 0.f;
    for (int i = l; i < 256; i += 32) t += g_diffpart[w * 256 + i];
#pragma unroll
    for (int o = 16; o > 0; o >>= 1) t += __shfl_down_sync(0xffffffffu, t, o);
    __shared__ float sb[8];
    if (l == 0) sb[w] = sqrtf(t);
    __syncthreads();
    if (tid == 0) {
        float mm = 0.f;
#pragma unroll
        for (int bb = 0; bb < 8; bb++) mm += sb[bb];
        mm *= 0.125f;
        if (!(mm >= TOL)) g_converged = 1;   // NaN also stops (matches jax)
    }
}

// ---------------------------------------------------------------------------
extern "C" void kernel_launch(void* const* d_in, const int* in_sizes, int n_in,
                              void* d_out, int out_size)
{
    const float* inp     = (const float*)d_in[0];
    const float* core_w1 = (const float*)d_in[1];
    const float* core_b1 = (const float*)d_in[2];
    const float* gn_w    = (const float*)d_in[3];
    const float* gn_b    = (const float*)d_in[4];
    const float* core_w2 = (const float*)d_in[5];
    const float* core_b2 = (const float*)d_in[6];
    const float* stab_w1 = (const float*)d_in[7];
    const float* stab_b1 = (const float*)d_in[8];
    const float* stab_w2 = (const float*)d_in[9];
    const float* stab_b2 = (const float*)d_in[10];
    const float* fc1_w   = (const float*)d_in[11];
    const float* fc1_b   = (const float*)d_in[12];
    const float* fc2_w   = (const float*)d_in[13];
    const float* fc2_b   = (const float*)d_in[14];
    float* out = (float*)d_out;

    dim3 blk(16, 16);
    dim3 grd(16, 16, BATCH);

    // convz is the 4th launch (ncu capture window)
    stab1_kernel<<<grd, blk>>>(inp, stab_w1, stab_b1, fc1_w, fc1_b, fc2_w, fc2_b);
    hfix_kernel<<<grd, blk>>>(inp, core_w1, core_b1);
    stab2_kernel<<<grd, blk>>>(stab_w2, stab_b2);
    convz_kernel<<<grd, blk>>>(core_w1, gn_w, gn_b, 1);
    fused2_kernel<<<grd, blk>>>(inp, core_w2, core_b2, nullptr, 0);

    for (int it = 1; it < MAX_ITER; ++it) {
        convz_kernel<<<grd, blk>>>(core_w1, gn_w, gn_b, 1);
        fused2_kernel<<<grd, blk>>>(inp, core_w2, core_b2, nullptr, 0);
    }
    // final core_f (always runs): z_star -> d_out
    convz_kernel<<<grd, blk>>>(core_w1, gn_w, gn_b, 0);
    fused2_kernel<<<grd, blk>>>(inp, core_w2, core_b2, out, 1);
}

// round 7
// speedup vs baseline: 1.2949x; 1.0238x over previous
#include <cuda_runtime.h>
#include <cuda_bf16.h>
#include <math.h>

// ---------------------------------------------------------------------------
// MultiDEQPDEBlock: DEQ fixed-point PDE solver  (B=8, 256x256, hid=32, GN4)
// core_f: conv3x3(4->32) -> GN(4) -> GELU(erf) -> conv3x3(32->1) -> damped update
// h_fixed (conv of loop-invariant [b,m,k]) precomputed once; per-iter conv1 is
// the 9-tap z convolution. fused2 h-staging is channel-batched (MLP16) to kill
// the rolled-loop latency bind. Divergent dynamics (|1-mask|>1) -> ~1e37;
// overflow paths mirror jax (var->inf, rstd->0, xn->0; NaN diff stops loop).
// ---------------------------------------------------------------------------

#define BATCH 8
#define HH 256
#define WW 256
#define PIX (HH*WW)
#define HID 32
#define SHID 16
#define GROUPS 4
#define CPG 8
#define EPS 1e-5f
#define TOL 1e-4f
#define MAX_ITER 50
#define CFL_SCALE 0.015625f
#define NBLK 2048               // (16,16,8) grids

// ---- scratch (device globals; no cudaMalloc allowed) ----
__device__ float g_h[(size_t)BATCH*HID*PIX];      // 64 MB conv1 output (pre-GN)
__device__ float g_hfix[(size_t)BATCH*HID*PIX];   // 64 MB conv of fixed channels
__device__ float g_sh[(size_t)BATCH*SHID*PIX];    // 32 MB stabilizer hidden
__device__ float g_alpha[(size_t)BATCH*PIX];
__device__ float g_z[(size_t)BATCH*PIX];
__device__ float g_gamma[BATCH];
__device__ float g_part[BATCH*256*GROUPS*2];
__device__ float g_spart[BATCH*256*4];
__device__ float g_scale[BATCH*HID];
__device__ float g_shift[BATCH*HID];
__device__ float g_diffpart[BATCH*256];
__device__ int   g_converged;
__device__ unsigned g_cnt0;     // zero-init; self-resetting via atomicInc wrap
__device__ unsigned g_cnt1;
__device__ unsigned g_cnt2;

__device__ __forceinline__ float gelu_f(float x) {
    return 0.5f * x * (1.0f + erff(x * 0.70710678118654752f));
}
__device__ __forceinline__ float sigmoid_f(float x) {
    return 1.0f / (1.0f + expf(-x));
}

// ---------------------------------------------------------------------------
// stabilizer conv1 (3->16, GELU) + z init + spec partials; last block: gamma MLP
// ---------------------------------------------------------------------------
__global__ void __launch_bounds__(256) stab1_kernel(
    const float* __restrict__ inp, const float* __restrict__ w,
    const float* __restrict__ bias,
    const float* __restrict__ fc1_w, const float* __restrict__ fc1_b,
    const float* __restrict__ fc2_w, const float* __restrict__ fc2_b)
{
    const int b = blockIdx.z;
    const int tx0 = blockIdx.x * 16, ty0 = blockIdx.y * 16;
    __shared__ float s_in[3][18][18];
    __shared__ float s_w[27][16];
    __shared__ float s_b[16];
    __shared__ float s_red[8][4];
    __shared__ bool s_last;
    int tid = threadIdx.y * 16 + threadIdx.x;

    if (tid == 0 && blockIdx.x == 0 && blockIdx.y == 0 && b == 0) g_converged = 0;

    for (int i = tid; i < SHID * 27; i += 256) {
        int oc = i / 27, r = i % 27;
        s_w[r][oc] = w[i];
    }
    if (tid < SHID) s_b[tid] = bias[tid];

    const float* bp = inp + (size_t)b * 3 * PIX;
    for (int i = tid; i < 3 * 324; i += 256) {
        int c = i / 324, r = i % 324, yy = r / 18, xx = r % 18;
        int gy = ty0 + yy - 1, gx = tx0 + xx - 1;
        float v = 0.f;
        if ((unsigned)gy < 256u && (unsigned)gx < 256u)
            v = bp[c * PIX + gy * WW + gx];
        s_in[c][yy][xx] = v;
    }
    __syncthreads();

    int ty = threadIdx.y, tx = threadIdx.x;
    float in[27];
#pragma unroll
    for (int c = 0; c < 3; c++)
#pragma unroll
        for (int ky = 0; ky < 3; ky++)
#pragma unroll
            for (int kx = 0; kx < 3; kx++)
                in[c * 9 + ky * 3 + kx] = s_in[c][ty + ky][tx + kx];

    float acc[SHID];
#pragma unroll
    for (int oc = 0; oc < SHID; oc++) acc[oc] = s_b[oc];
#pragma unroll
    for (int r = 0; r < 27; r++) {
        float iv = in[r];
#pragma unroll
        for (int oc = 0; oc < SHID; oc++) acc[oc] += iv * s_w[r][oc];
    }

    int pix = (ty0 + ty) * WW + (tx0 + tx);
    float* out = g_sh + (size_t)b * SHID * PIX + pix;
#pragma unroll
    for (int oc = 0; oc < SHID; oc++)
        out[oc * PIX] = gelu_f(acc[oc]);

    // z init (channel 0 = boundary)
    g_z[b * PIX + pix] = s_in[0][ty + 1][tx + 1];

    // spec partials: |boundary| and k stats
    float bv = fabsf(s_in[0][ty + 1][tx + 1]);
    float kv = s_in[2][ty + 1][tx + 1];
    float s1 = bv, q1 = bv * bv, s2 = kv, q2 = kv * kv;
#pragma unroll
    for (int o = 16; o > 0; o >>= 1) {
        s1 += __shfl_down_sync(0xffffffffu, s1, o);
        q1 += __shfl_down_sync(0xffffffffu, q1, o);
        s2 += __shfl_down_sync(0xffffffffu, s2, o);
        q2 += __shfl_down_sync(0xffffffffu, q2, o);
    }
    int lane = tid & 31, warp = tid >> 5;
    if (lane == 0) { s_red[warp][0] = s1; s_red[warp][1] = q1; s_red[warp][2] = s2; s_red[warp][3] = q2; }
    __syncthreads();
    int blin = blockIdx.y * 16 + blockIdx.x;
    if (tid < 4) {
        float v = 0.f;
#pragma unroll
        for (int w8 = 0; w8 < 8; w8++) v += s_red[w8][tid];
        g_spart[(b * 256 + blin) * 4 + tid] = v;
        __threadfence();
    }
    __syncthreads();
    if (tid == 0) {
        unsigned old = atomicInc(&g_cnt0, NBLK - 1u);
        s_last = (old == NBLK - 1u);
    }
    __syncthreads();
    if (!s_last) return;
    __threadfence();

    // last block: per-batch spec_ctrl MLP -> gamma (warp w = batch w)
    int w8 = tid >> 5, l = tid & 31;
    float S1 = 0, Q1 = 0, S2 = 0, Q2 = 0;
    for (int i = l; i < 256; i += 32) {
        S1 += g_spart[(w8 * 256 + i) * 4 + 0];
        Q1 += g_spart[(w8 * 256 + i) * 4 + 1];
        S2 += g_spart[(w8 * 256 + i) * 4 + 2];
        Q2 += g_spart[(w8 * 256 + i) * 4 + 3];
    }
#pragma unroll
    for (int o = 16; o > 0; o >>= 1) {
        S1 += __shfl_down_sync(0xffffffffu, S1, o);
        Q1 += __shfl_down_sync(0xffffffffu, Q1, o);
        S2 += __shfl_down_sync(0xffffffffu, S2, o);
        Q2 += __shfl_down_sync(0xffffffffu, Q2, o);
    }
    if (l == 0) {
        const float N = (float)PIX;
        float m1 = S1 / N, m2 = S2 / N;
        float v1 = (Q1 - N * m1 * m1) / (N - 1.0f);
        float v2 = (Q2 - N * m2 * m2) / (N - 1.0f);
        float feat[5] = { m1, sqrtf(fmaxf(v1, 0.f)), m2, sqrtf(fmaxf(v2, 0.f)), 1.0f };
        float outv = fc2_b[0];
        for (int j = 0; j < 32; j++) {
            float t = fc1_b[j];
#pragma unroll
            for (int i = 0; i < 5; i++) t += feat[i] * fc1_w[j * 5 + i];
            outv += gelu_f(t) * fc2_w[j];
        }
        g_gamma[w8] = (0.5f + 1.5f * sigmoid_f(outv)) * CFL_SCALE;
    }
}

// ---------------------------------------------------------------------------
// prep: stab2 (16->1 sigmoid -> alpha)  AND  hfix (conv3x3 of [b,m,k] + bias)
// merged one-time kernel (keeps fused2 as the 4th launch for ncu)
// ---------------------------------------------------------------------------
__global__ void __launch_bounds__(256) prep_kernel(
    const float* __restrict__ inp,
    const float* __restrict__ w2s, const float* __restrict__ b2s,
    const float* __restrict__ w1, const float* __restrict__ b1)
{
    const int b = blockIdx.z;
    const int tx0 = blockIdx.x * 16, ty0 = blockIdx.y * 16;
    __shared__ float s_sh[SHID][18][18];
    __shared__ float s_in[3][18][18];
    __shared__ float s_ws[SHID * 9];
    __shared__ __align__(16) float s_wh[27][32];
    __shared__ float s_bh[32];
    int tid = threadIdx.y * 16 + threadIdx.x;

    if (tid < SHID * 9) s_ws[tid] = w2s[tid];
    for (int i = tid; i < HID * 27; i += 256) {
        int oc = i / 27, r = i % 27;
        s_wh[r][oc] = w1[oc * 36 + 9 + r];   // skip z-channel taps
    }
    if (tid < HID) s_bh[tid] = b1[tid];

    const float* hp = g_sh + (size_t)b * SHID * PIX;
    for (int i = tid; i < SHID * 324; i += 256) {
        int c = i / 324, r = i % 324, yy = r / 18, xx = r % 18;
        int gy = ty0 + yy - 1, gx = tx0 + xx - 1;
        float v = 0.f;
        if ((unsigned)gy < 256u && (unsigned)gx < 256u)
            v = hp[c * PIX + gy * WW + gx];
        s_sh[c][yy][xx] = v;
    }
    const float* bp = inp + (size_t)b * 3 * PIX;
    for (int i = tid; i < 3 * 324; i += 256) {
        int c = i / 324, r = i % 324, yy = r / 18, xx = r % 18;
        int gy = ty0 + yy - 1, gx = tx0 + xx - 1;
        float v = 0.f;
        if ((unsigned)gy < 256u && (unsigned)gx < 256u)
            v = bp[c * PIX + gy * WW + gx];
        s_in[c][yy][xx] = v;
    }
    __syncthreads();

    int ty = threadIdx.y, tx = threadIdx.x;
    int pix = (ty0 + ty) * WW + (tx0 + tx);

    // stab2: alpha
    {
        float acc = b2s[0];
#pragma unroll
        for (int c = 0; c < SHID; c++)
#pragma unroll
            for (int ky = 0; ky < 3; ky++)
#pragma unroll
                for (int kx = 0; kx < 3; kx++)
                    acc += s_ws[c * 9 + ky * 3 + kx] * s_sh[c][ty + ky][tx + kx];
        g_alpha[(size_t)b * PIX + pix] = sigmoid_f(acc);
    }

    // hfix: 27-tap conv of fixed channels into 32 outputs
    {
        float acc[HID];
#pragma unroll
        for (int oc = 0; oc < HID; oc++) acc[oc] = s_bh[oc];
#pragma unroll
        for (int c = 0; c < 3; c++)
#pragma unroll
            for (int ky = 0; ky < 3; ky++)
#pragma unroll
                for (int kx = 0; kx < 3; kx++) {
                    float iv = s_in[c][ty + ky][tx + kx];
                    int r = c * 9 + ky * 3 + kx;
#pragma unroll
                    for (int j = 0; j < 8; j++) {
                        float4 w4 = ((const float4*)&s_wh[r][0])[j];
                        acc[4*j+0] += iv * w4.x; acc[4*j+1] += iv * w4.y;
                        acc[4*j+2] += iv * w4.z; acc[4*j+3] += iv * w4.w;
                    }
                }
        float* op = g_hfix + (size_t)b * HID * PIX + pix;
#pragma unroll
        for (int oc = 0; oc < HID; oc++) op[oc * PIX] = acc[oc];
    }
}

// ---------------------------------------------------------------------------
// convz: h = h_fixed + conv3x3(z, w1[:,0])  (9 taps), write g_h + GN partials;
// LAST BLOCK folds GN stats -> scale/shift.
// ---------------------------------------------------------------------------
__global__ void __launch_bounds__(256, 4) convz_kernel(
    const float* __restrict__ w1, const float* __restrict__ gn_w,
    const float* __restrict__ gn_b, int check)
{
    if (check && g_converged) return;
    const int b = blockIdx.z;
    const int tx0 = blockIdx.x * 16, ty0 = blockIdx.y * 16;
    __shared__ float s_z[18][18];
    __shared__ __align__(16) float s_w[9][32];
    __shared__ float s_red[8][8];
    __shared__ bool s_last;
    int tid = threadIdx.y * 16 + threadIdx.x;

    for (int i = tid; i < HID * 9; i += 256) {
        int oc = i / 9, r = i % 9;
        s_w[r][oc] = w1[oc * 36 + r];       // z-channel taps (c=0)
    }

    const float* zp = g_z + (size_t)b * PIX;
    for (int i = tid; i < 324; i += 256) {
        int yy = i / 18, xx = i % 18;
        int gy = ty0 + yy - 1, gx = tx0 + xx - 1;
        float v = 0.f;
        if ((unsigned)gy < 256u && (unsigned)gx < 256u)
            v = zp[gy * WW + gx];
        s_z[yy][xx] = v;
    }
    __syncthreads();

    int ty = threadIdx.y, tx = threadIdx.x;
    float zv[9];
#pragma unroll
    for (int ky = 0; ky < 3; ky++)
#pragma unroll
        for (int kx = 0; kx < 3; kx++)
            zv[ky * 3 + kx] = s_z[ty + ky][tx + kx];

    int pix = (ty0 + ty) * WW + (tx0 + tx);
    const float* fp = g_hfix + (size_t)b * HID * PIX + pix;
    float acc[HID];
#pragma unroll
    for (int oc = 0; oc < HID; oc++) acc[oc] = fp[oc * PIX];
#pragma unroll
    for (int r = 0; r < 9; r++) {
        float iv = zv[r];
#pragma unroll
        for (int j = 0; j < 8; j++) {
            float4 w4 = ((const float4*)&s_w[r][0])[j];
            acc[4*j+0] += iv * w4.x; acc[4*j+1] += iv * w4.y;
            acc[4*j+2] += iv * w4.z; acc[4*j+3] += iv * w4.w;
        }
    }

    float* hp = g_h + (size_t)b * HID * PIX + pix;
    float gs[4] = {0, 0, 0, 0}, gq[4] = {0, 0, 0, 0};
#pragma unroll
    for (int oc = 0; oc < HID; oc++) {
        float v = acc[oc];
        hp[oc * PIX] = v;
        gs[oc >> 3] += v;
        gq[oc >> 3] += v * v;
    }
#pragma unroll
    for (int o = 16; o > 0; o >>= 1) {
#pragma unroll
        for (int g = 0; g < 4; g++) {
            gs[g] += __shfl_down_sync(0xffffffffu, gs[g], o);
            gq[g] += __shfl_down_sync(0xffffffffu, gq[g], o);
        }
    }
    int lane = tid & 31, warp = tid >> 5;
    if (lane == 0) {
#pragma unroll
        for (int g = 0; g < 4; g++) { s_red[warp][g] = gs[g]; s_red[warp][4 + g] = gq[g]; }
    }
    __syncthreads();
    int blin = blockIdx.y * 16 + blockIdx.x;
    if (tid < 8) {
        float v = 0.f;
#pragma unroll
        for (int w = 0; w < 8; w++) v += s_red[w][tid];
        int g = tid & 3, which = tid >> 2;
        g_part[((b * 256 + blin) * 4 + g) * 2 + which] = v;
        __threadfence();
    }
    __syncthreads();
    if (tid == 0) {
        unsigned old = atomicInc(&g_cnt1, NBLK - 1u);
        s_last = (old == NBLK - 1u);
    }
    __syncthreads();
    if (!s_last) return;
    __threadfence();

    // last block: fold GN stats for all 32 (b,g) pairs; 8 lanes per pair
    int pair = tid >> 3, l8 = tid & 7;
    int bb = pair >> 2, g = pair & 3;
    float s = 0.f, q = 0.f;
    for (int i = l8; i < 256; i += 8) {
        s += g_part[((bb * 256 + i) * 4 + g) * 2 + 0];
        q += g_part[((bb * 256 + i) * 4 + g) * 2 + 1];
    }
#pragma unroll
    for (int o = 4; o > 0; o >>= 1) {
        s += __shfl_down_sync(0xffffffffu, s, o, 8);
        q += __shfl_down_sync(0xffffffffu, q, o, 8);
    }
    if (l8 == 0) {
        const float invN = 1.0f / (float)(CPG * PIX);
        float mean = s * invN;
        float Qn = q * invN;
        float var = isinf(Qn) ? Qn : fmaxf(Qn - mean * mean, 0.0f);
        float rstd = rsqrtf(var + EPS);       // var=inf -> rstd=0
#pragma unroll
        for (int c = 0; c < CPG; c++) {
            int gc = g * CPG + c;
            float sc = gn_w[gc] * rstd;
            g_scale[bb * HID + gc] = sc;
            g_shift[bb * HID + gc] = (rstd == 0.0f) ? gn_b[gc] : (gn_b[gc] - mean * sc);
        }
    }
}

// ---------------------------------------------------------------------------
// fused2: GN->GELU->conv2(32->1)->damped update; LAST BLOCK folds diff.
// h staging: 1 fixed pixel/thread, channel-unrolled batches of 16 (MLP 16).
// ---------------------------------------------------------------------------
// fill one pixel p (yy,xx) for channels [base, base+16)
#define FILL16(base, yy, xx, inb, hbase)                                   \
    {                                                                      \
        float hv[16];                                                      \
        _Pragma("unroll")                                                  \
        for (int c = 0; c < 16; c++)                                       \
            hv[c] = (inb) ? (hbase)[(size_t)(base + c) * PIX] : 0.f;       \
        _Pragma("unroll")                                                  \
        for (int c = 0; c < 16; c++) {                                     \
            float sc = s_sc[base + c];                                     \
            float t = (sc == 0.0f) ? s_sf[base + c]                        \
                                   : (hv[c] * sc + s_sf[base + c]);        \
            s_h[base + c][yy][xx] = (inb) ? gelu_f(t) : 0.f;               \
        }                                                                  \
    }

__global__ void __launch_bounds__(256) fused2_kernel(
    const float* __restrict__ inp, const float* __restrict__ w2,
    const float* __restrict__ b2, float* __restrict__ final_out, int mode)
{
    if (mode == 0 && g_converged) return;
    const int b = blockIdx.z;
    const int tx0 = blockIdx.x * 16, ty0 = blockIdx.y * 16;
    __shared__ float s_h[HID][18][18];
    __shared__ float s_w[HID * 9];
    __shared__ float s_sc[HID], s_sf[HID];
    __shared__ float s_red[8];
    __shared__ bool s_last;
    int tid = threadIdx.y * 16 + threadIdx.x;

    for (int i = tid; i < HID * 9; i += 256) s_w[i] = w2[i];
    if (tid < HID) { s_sc[tid] = g_scale[b * HID + tid]; s_sf[tid] = g_shift[b * HID + tid]; }
    __syncthreads();

    const float* hp = g_h + (size_t)b * HID * PIX;
    {
        // pixel 1: p = tid (tid < 324 always)
        int yy = tid / 18, xx = tid % 18;
        int gy = ty0 + yy - 1, gx = tx0 + xx - 1;
        bool inb = ((unsigned)gy < 256u) && ((unsigned)gx < 256u);
        const float* hb = hp + (inb ? (gy * WW + gx) : 0);
        FILL16(0, yy, xx, inb, hb)
        FILL16(16, yy, xx, inb, hb)
        // pixel 2: p = tid + 256 (only tid < 68)
        if (tid < 68) {
            int p2 = tid + 256;
            int yy2 = p2 / 18, xx2 = p2 % 18;
            int gy2 = ty0 + yy2 - 1, gx2 = tx0 + xx2 - 1;
            bool inb2 = ((unsigned)gy2 < 256u) && ((unsigned)gx2 < 256u);
            const float* hb2 = hp + (inb2 ? (gy2 * WW + gx2) : 0);
            FILL16(0, yy2, xx2, inb2, hb2)
            FILL16(16, yy2, xx2, inb2, hb2)
        }
    }
    __syncthreads();

    int ty = threadIdx.y, tx = threadIdx.x;
    float a0 = 0.f, a1 = 0.f, a2 = 0.f, a3 = 0.f;   // 4 ILP chains over c%4
#pragma unroll
    for (int c = 0; c < HID; c += 4) {
#pragma unroll
        for (int ky = 0; ky < 3; ky++)
#pragma unroll
            for (int kx = 0; kx < 3; kx++) {
                int pos = ky * 3 + kx;
                a0 += s_w[(c + 0) * 9 + pos] * s_h[c + 0][ty + ky][tx + kx];
                a1 += s_w[(c + 1) * 9 + pos] * s_h[c + 1][ty + ky][tx + kx];
                a2 += s_w[(c + 2) * 9 + pos] * s_h[c + 2][ty + ky][tx + kx];
                a3 += s_w[(c + 3) * 9 + pos] * s_h[c + 3][ty + ky][tx + kx];
            }
    }
    float acc = b2[0] + ((a0 + a1) + (a2 + a3));

    int pix = (ty0 + ty) * WW + (tx0 + tx);
    int off = b * PIX + pix;
    const float* bp = inp + (size_t)b * 3 * PIX;
    float zold = g_z[off];
    // mirror XLA elementwise rounding exactly (no FMA contraction)
    float ga   = __fmul_rn(g_gamma[b], g_alpha[off]);
    float znew = __fadd_rn(zold, __fmul_rn(ga, acc));
    float m  = bp[PIX + pix];
    float bv = bp[pix];
    float res = __fadd_rn(__fmul_rn(znew, __fadd_rn(1.0f, -m)), __fmul_rn(bv, m));

    if (mode != 0) { final_out[off] = res; return; }

    g_z[off] = res;
    float d = __fadd_rn(res, -zold);
    float s = d * d;
#pragma unroll
    for (int o = 16; o > 0; o >>= 1) s += __shfl_down_sync(0xffffffffu, s, o);
    int lane = tid & 31, warp = tid >> 5;
    if (lane == 0) s_red[warp] = s;
    __syncthreads();
    int blin = blockIdx.y * 16 + blockIdx.x;
    if (tid == 0) {
        float t = 0.f;
#pragma unroll
        for (int w = 0; w < 8; w++) t += s_red[w];
        g_diffpart[b * 256 + blin] = t;
        __threadfence();
        unsigned old = atomicInc(&g_cnt2, NBLK - 1u);
        s_last = (old == NBLK - 1u);
    }
    __syncthreads();
    if (!s_last) return;
    __threadfence();

    // last block: diff = mean_b ||dz_b||; jax cond continues while diff>=TOL
    int w = tid >> 5, l = tid & 31;
    float t = 0.f;
    for (int i = l; i < 256; i += 32) t += g_diffpart[w * 256 + i];
#pragma unroll
    for (int o = 16; o > 0; o >>= 1) t += __shfl_down_sync(0xffffffffu, t, o);
    __shared__ float sb[8];
    if (l == 0) sb[w] = sqrtf(t);
    __syncthreads();
    if (tid == 0) {
        float mm = 0.f;
#pragma unroll
        for (int bb = 0; bb < 8; bb++) mm += sb[bb];
        mm *= 0.125f;
        if (!(mm >= TOL)) g_converged = 1;   // NaN also stops (matches jax)
    }
}

// ---------------------------------------------------------------------------
extern "C" void kernel_launch(void* const* d_in, const int* in_sizes, int n_in,
                              void* d_out, int out_size)
{
    const float* inp     = (const float*)d_in[0];
    const float* core_w1 = (const float*)d_in[1];
    const float* core_b1 = (const float*)d_in[2];
    const float* gn_w    = (const float*)d_in[3];
    const float* gn_b    = (const float*)d_in[4];
    const float* core_w2 = (const float*)d_in[5];
    const float* core_b2 = (const float*)d_in[6];
    const float* stab_w1 = (const float*)d_in[7];
    const float* stab_b1 = (const float*)d_in[8];
    const float* stab_w2 = (const float*)d_in[9];
    const float* stab_b2 = (const float*)d_in[10];
    const float* fc1_w   = (const float*)d_in[11];
    const float* fc1_b   = (const float*)d_in[12];
    const float* fc2_w   = (const float*)d_in[13];
    const float* fc2_b   = (const float*)d_in[14];
    float* out = (float*)d_out;

    dim3 blk(16, 16);
    dim3 grd(16, 16, BATCH);

    // fused2 is the 4th launch (ncu capture window)
    stab1_kernel<<<grd, blk>>>(inp, stab_w1, stab_b1, fc1_w, fc1_b, fc2_w, fc2_b);
    prep_kernel<<<grd, blk>>>(inp, stab_w2, stab_b2, core_w1, core_b1);
    convz_kernel<<<grd, blk>>>(core_w1, gn_w, gn_b, 1);
    fused2_kernel<<<grd, blk>>>(inp, core_w2, core_b2, nullptr, 0);

    for (int it = 1; it < MAX_ITER; ++it) {
        convz_kernel<<<grd, blk>>>(core_w1, gn_w, gn_b, 1);
        fused2_kernel<<<grd, blk>>>(inp, core_w2, core_b2, nullptr, 0);
    }
    // final core_f (always runs): z_star -> d_out
    convz_kernel<<<grd, blk>>>(core_w1, gn_w, gn_b, 0);
    fused2_kernel<<<grd, blk>>>(inp, core_w2, core_b2, out, 1);
}